// round 1
// baseline (speedup 1.0000x reference)
#include <cuda_runtime.h>

// LIF scan over time axis. x: [B, F, T] fp32 with T=100 contiguous.
// out[b,f,t] = spike in {0,1}.
// Recurrence per row: mem = (mem*DECAY)*(1-spike) + x[t]; spike = mem > THRESH.

#define LIF_THRESH 0.5f
#define LIF_DECAY  0.2f
#define LIF_T      100
#define LIF_TV     (LIF_T / 4)   // 25 float4 per row (odd -> conflict-free LDS.128)
#define LIF_ROWS   64            // rows (threads) per block; smem = 64*100*4 = 25.6 KB

__global__ __launch_bounds__(LIF_ROWS)
void lif_scan_kernel(const float4* __restrict__ x, float4* __restrict__ out) {
    // Linear smem layout == linear global layout for this block's 64 rows,
    // so the copy is a straight coalesced memcpy and the row-major view
    // s[row*25 + k] needs no padding: stride 25 (odd) is bank-conflict-free
    // for 128-bit shared accesses.
    __shared__ float4 s[LIF_ROWS * LIF_TV];

    const int tid = threadIdx.x;
    const size_t base = (size_t)blockIdx.x * (LIF_ROWS * LIF_TV);

    // ---- coalesced copy-in: 25 x LDG.128 per thread, linear ----
    #pragma unroll
    for (int i = 0; i < LIF_TV; i++) {
        s[i * LIF_ROWS + tid] = x[base + i * LIF_ROWS + tid];
    }
    __syncthreads();

    // ---- per-thread sequential LIF scan over this thread's row ----
    float mem = 0.0f;
    float sp  = 0.0f;
    float4* row = s + (size_t)tid * LIF_TV;
    #pragma unroll
    for (int k = 0; k < LIF_TV; k++) {
        float4 v = row[k];
        float4 o;
        // Forced mul-mul-add rounding (no FMA contraction) to match the
        // reference: ((mem*DECAY)*(1-sp)) + x
        mem = __fadd_rn(__fmul_rn(__fmul_rn(mem, LIF_DECAY), 1.0f - sp), v.x);
        sp  = (mem > LIF_THRESH) ? 1.0f : 0.0f;  o.x = sp;
        mem = __fadd_rn(__fmul_rn(__fmul_rn(mem, LIF_DECAY), 1.0f - sp), v.y);
        sp  = (mem > LIF_THRESH) ? 1.0f : 0.0f;  o.y = sp;
        mem = __fadd_rn(__fmul_rn(__fmul_rn(mem, LIF_DECAY), 1.0f - sp), v.z);
        sp  = (mem > LIF_THRESH) ? 1.0f : 0.0f;  o.z = sp;
        mem = __fadd_rn(__fmul_rn(__fmul_rn(mem, LIF_DECAY), 1.0f - sp), v.w);
        sp  = (mem > LIF_THRESH) ? 1.0f : 0.0f;  o.w = sp;
        row[k] = o;  // spikes written back in place
    }
    __syncthreads();

    // ---- coalesced copy-out ----
    #pragma unroll
    for (int i = 0; i < LIF_TV; i++) {
        out[base + i * LIF_ROWS + tid] = s[i * LIF_ROWS + tid];
    }
}

// Scalar fallback for any remainder rows (not expected for the fixed shape,
// but keeps the kernel correct for any row count divisible by nothing).
__global__ void lif_scan_tail_kernel(const float* __restrict__ x,
                                     float* __restrict__ out,
                                     long long row_start, long long n_rows) {
    long long r = row_start + blockIdx.x * (long long)blockDim.x + threadIdx.x;
    if (r >= n_rows) return;
    const float* xr = x + r * LIF_T;
    float* orow = out + r * LIF_T;
    float mem = 0.0f, sp = 0.0f;
    #pragma unroll 4
    for (int t = 0; t < LIF_T; t++) {
        mem = __fadd_rn(__fmul_rn(__fmul_rn(mem, LIF_DECAY), 1.0f - sp), xr[t]);
        sp  = (mem > LIF_THRESH) ? 1.0f : 0.0f;
        orow[t] = sp;
    }
}

extern "C" void kernel_launch(void* const* d_in, const int* in_sizes, int n_in,
                              void* d_out, int out_size) {
    const float* x = (const float*)d_in[0];
    float* out = (float*)d_out;

    long long total = (long long)in_sizes[0];
    long long n_rows = total / LIF_T;           // 524288 for the fixed shape
    long long full_blocks = n_rows / LIF_ROWS;  // 8192

    if (full_blocks > 0) {
        lif_scan_kernel<<<(unsigned)full_blocks, LIF_ROWS>>>(
            (const float4*)x, (float4*)out);
    }
    long long rem = n_rows - full_blocks * LIF_ROWS;
    if (rem > 0) {
        int threads = 128;
        int blocks = (int)((rem + threads - 1) / threads);
        lif_scan_tail_kernel<<<blocks, threads>>>(
            x, out, full_blocks * LIF_ROWS, n_rows);
    }
}

// round 2
// speedup vs baseline: 1.0997x; 1.0997x over previous
#include <cuda_runtime.h>
#include <cstdint>

// LIF scan over time axis. x: [rows, T=100] fp32, T contiguous.
// Recurrence per row: mem = (mem*DECAY)*(1-spike) + x[t]; spike = mem > THRESH.
//
// R2 design: bulk-TMA streaming. Each block's chunk (128 rows x 400 B) is
// CONTIGUOUS in global memory -> one cp.async.bulk per chunk each way.
// Double-buffered input ring (mbarrier/expect_tx) + double-buffered output
// ring (bulk_group / wait_group.read). SM does only LDS + scan + STS.

#define LIF_THRESH 0.5f
#define LIF_DECAY  0.2f
#define LIF_T      100
#define LIF_TV     25                       // float4 per row (odd -> conflict-free)
#define CHUNK_ROWS 128
#define THREADS    128
#define CHUNK_BYTES (CHUNK_ROWS * LIF_T * 4)   // 51200
// dynamic smem layout (bytes)
#define SM_MBAR 0                              // 2 x 8B mbarriers
#define SM_IN   1024
#define SM_OUT  (SM_IN + 2 * CHUNK_BYTES)
#define SM_TOTAL (SM_OUT + 2 * CHUNK_BYTES)    // 1024 + 4*51200 = 205824

__device__ __forceinline__ uint32_t smem_u32(const void* p) {
    uint32_t a;
    asm("{ .reg .u64 t; cvta.to.shared.u64 t, %1; cvt.u32.u64 %0, t; }" : "=r"(a) : "l"(p));
    return a;
}
__device__ __forceinline__ void mbar_init(uint32_t mbar, uint32_t cnt) {
    asm volatile("mbarrier.init.shared.b64 [%0], %1;" :: "r"(mbar), "r"(cnt) : "memory");
}
__device__ __forceinline__ void mbar_expect(uint32_t mbar, uint32_t bytes) {
    asm volatile("mbarrier.arrive.expect_tx.shared.b64 _, [%0], %1;" :: "r"(mbar), "r"(bytes) : "memory");
}
__device__ __forceinline__ void mbar_wait(uint32_t mbar, uint32_t parity) {
    uint32_t done;
    asm volatile(
        "{\n\t.reg .pred p;\n\t"
        "mbarrier.try_wait.parity.acquire.cta.shared::cta.b64 p, [%1], %2;\n\t"
        "selp.b32 %0, 1, 0, p;\n\t}"
        : "=r"(done) : "r"(mbar), "r"(parity) : "memory");
    if (!done) {
        asm volatile(
            "{\n\t.reg .pred P1;\n\t"
            "W_%=:\n\t"
            "mbarrier.try_wait.parity.acquire.cta.shared::cta.b64 P1, [%0], %1, 0x989680;\n\t"
            "@P1 bra.uni D_%=;\n\t"
            "bra.uni W_%=;\n\t"
            "D_%=:\n\t}"
            :: "r"(mbar), "r"(parity) : "memory");
    }
}
__device__ __forceinline__ void bulk_g2s(uint32_t dst_smem, const void* src, uint32_t bytes, uint32_t mbar) {
    asm volatile(
        "cp.async.bulk.shared::cluster.global.mbarrier::complete_tx::bytes [%0], [%1], %2, [%3];"
        :: "r"(dst_smem), "l"(src), "r"(bytes), "r"(mbar) : "memory");
}
__device__ __forceinline__ void bulk_s2g(void* dst, uint32_t src_smem, uint32_t bytes) {
    asm volatile(
        "cp.async.bulk.global.shared::cta.bulk_group [%0], [%1], %2;"
        :: "l"(dst), "r"(src_smem), "r"(bytes) : "memory");
}

__global__ __launch_bounds__(THREADS, 1)
void lif_tma_kernel(const char* __restrict__ gin, char* __restrict__ gout,
                    int n_chunks, int chunks_per_block) {
    extern __shared__ char smem[];
    const uint32_t sbase = smem_u32(smem);
    const int tid = threadIdx.x;

    long long first = (long long)blockIdx.x * chunks_per_block;
    int nc = 0;
    if (first < n_chunks) {
        long long rem = n_chunks - first;
        nc = rem < chunks_per_block ? (int)rem : chunks_per_block;
    }
    if (nc == 0) return;

    const uint32_t mbar0 = sbase + SM_MBAR;
    const uint32_t mbar1 = sbase + SM_MBAR + 8;

    if (tid == 0) {
        mbar_init(mbar0, 1);
        mbar_init(mbar1, 1);
        asm volatile("fence.proxy.async.shared::cta;" ::: "memory");
    }
    __syncthreads();

    // Prologue: fill both input buffers.
    if (tid == 0) {
        mbar_expect(mbar0, CHUNK_BYTES);
        bulk_g2s(sbase + SM_IN, gin + first * (long long)CHUNK_BYTES, CHUNK_BYTES, mbar0);
        if (nc > 1) {
            mbar_expect(mbar1, CHUNK_BYTES);
            bulk_g2s(sbase + SM_IN + CHUNK_BYTES,
                     gin + (first + 1) * (long long)CHUNK_BYTES, CHUNK_BYTES, mbar1);
        }
    }

    uint32_t ph0 = 0, ph1 = 0;

    for (int c = 0; c < nc; c++) {
        const int b = c & 1;
        const uint32_t mb = b ? mbar1 : mbar0;

        // Wait for input chunk c.
        mbar_wait(mb, b ? ph1 : ph0);
        if (b) ph1 ^= 1; else ph0 ^= 1;

        // Pull my row into registers (stride 25 f4: conflict-free LDS.128).
        const float4* irow =
            (const float4*)(smem + SM_IN + b * CHUNK_BYTES) + tid * LIF_TV;
        float4 v[LIF_TV];
        #pragma unroll
        for (int k = 0; k < LIF_TV; k++) v[k] = irow[k];

        // Ensure out-buffer b (store of chunk c-2) is fully read by TMA.
        if (tid == 0)
            asm volatile("cp.async.bulk.wait_group.read 1;" ::: "memory");
        __syncthreads();   // publishes: inbuf[b] consumed, outbuf[b] free

        // Re-arm input buffer b for chunk c+2.
        if (tid == 0 && c + 2 < nc) {
            mbar_expect(mb, CHUNK_BYTES);
            bulk_g2s(sbase + SM_IN + b * CHUNK_BYTES,
                     gin + (first + c + 2) * (long long)CHUNK_BYTES, CHUNK_BYTES, mb);
        }

        // Sequential LIF scan, spikes to the out buffer.
        float4* orow = (float4*)(smem + SM_OUT + b * CHUNK_BYTES) + tid * LIF_TV;
        float mem = 0.0f, sp = 0.0f;
        #pragma unroll
        for (int k = 0; k < LIF_TV; k++) {
            float4 o;
            mem = __fadd_rn(__fmul_rn(__fmul_rn(mem, LIF_DECAY), 1.0f - sp), v[k].x);
            sp = (mem > LIF_THRESH) ? 1.0f : 0.0f; o.x = sp;
            mem = __fadd_rn(__fmul_rn(__fmul_rn(mem, LIF_DECAY), 1.0f - sp), v[k].y);
            sp = (mem > LIF_THRESH) ? 1.0f : 0.0f; o.y = sp;
            mem = __fadd_rn(__fmul_rn(__fmul_rn(mem, LIF_DECAY), 1.0f - sp), v[k].z);
            sp = (mem > LIF_THRESH) ? 1.0f : 0.0f; o.z = sp;
            mem = __fadd_rn(__fmul_rn(__fmul_rn(mem, LIF_DECAY), 1.0f - sp), v[k].w);
            sp = (mem > LIF_THRESH) ? 1.0f : 0.0f; o.w = sp;
            orow[k] = o;
        }

        // Publish STS to async proxy, then issue bulk store.
        asm volatile("fence.proxy.async.shared::cta;" ::: "memory");
        __syncthreads();
        if (tid == 0) {
            bulk_s2g(gout + (first + c) * (long long)CHUNK_BYTES,
                     sbase + SM_OUT + b * CHUNK_BYTES, CHUNK_BYTES);
            asm volatile("cp.async.bulk.commit_group;" ::: "memory");
        }
    }

    // Keep smem alive until all pending bulk stores have read it.
    if (tid == 0)
        asm volatile("cp.async.bulk.wait_group.read 0;" ::: "memory");
}

// Scalar tail for rows not covered by full chunks.
__global__ void lif_scan_tail_kernel(const float* __restrict__ x,
                                     float* __restrict__ out,
                                     long long row_start, long long n_rows) {
    long long r = row_start + blockIdx.x * (long long)blockDim.x + threadIdx.x;
    if (r >= n_rows) return;
    const float* xr = x + r * LIF_T;
    float* orow = out + r * LIF_T;
    float mem = 0.0f, sp = 0.0f;
    #pragma unroll 4
    for (int t = 0; t < LIF_T; t++) {
        mem = __fadd_rn(__fmul_rn(__fmul_rn(mem, LIF_DECAY), 1.0f - sp), xr[t]);
        sp = (mem > LIF_THRESH) ? 1.0f : 0.0f;
        orow[t] = sp;
    }
}

extern "C" void kernel_launch(void* const* d_in, const int* in_sizes, int n_in,
                              void* d_out, int out_size) {
    const float* x = (const float*)d_in[0];
    float* out = (float*)d_out;

    long long total = (long long)in_sizes[0];
    long long n_rows = total / LIF_T;                 // 524288
    long long n_chunks = n_rows / CHUNK_ROWS;         // 4096

    if (n_chunks > 0) {
        static int smem_set = 0;
        if (!smem_set) {
            cudaFuncSetAttribute(lif_tma_kernel,
                                 cudaFuncAttributeMaxDynamicSharedMemorySize, SM_TOTAL);
            smem_set = 1;
        }
        int grid = 256;
        if (n_chunks < grid) grid = (int)n_chunks;
        int cpb = (int)((n_chunks + grid - 1) / grid);  // 16 for the fixed shape
        lif_tma_kernel<<<grid, THREADS, SM_TOTAL>>>(
            (const char*)x, (char*)out, (int)n_chunks, cpb);
    }

    long long done_rows = n_chunks * CHUNK_ROWS;
    long long rem = n_rows - done_rows;
    if (rem > 0) {
        int threads = 128;
        int blocks = (int)((rem + threads - 1) / threads);
        lif_scan_tail_kernel<<<blocks, threads>>>(x, out, done_rows, n_rows);
    }
}